// round 12
// baseline (speedup 1.0000x reference)
#include <cuda_runtime.h>
#include <cuda_bf16.h>

// out[b,h,i,j] = mask[b,h,i,j] - |slope(h) * (i - j)|
// B=2, NH=16, L=2048. HBM-bound: 512 MiB read + 512 MiB write.
//
// R9: R3 layout (empirical best: ~150us ncu, DRAM ~86%), probing the last
// untried cache-op cell: DEFAULT loads (L2 keeps read sectors normally)
// + __stcs stores (evict-first writes). Everything else identical:
//   - 8 contiguous rows per block (64KB footprint), 512 threads
//   - front-batched 8 independent LDG.128 per thread (MLP_p1=8)
//   - non-persistent fire-and-forget blocks (wave overlap of loads/stores)

#define ROWS_PER_BLK 8

__global__ __launch_bounds__(512) void alibi_kernel(
    const float* __restrict__ mask,
    float* __restrict__ out,
    int L)
{
    // Base row for this block; all 8 rows share (b,h) since L % 8 == 0.
    const int rb = blockIdx.x * ROWS_PER_BLK;
    const int i0 = rb & (2048 - 1);          // rb % L, L=2048
    const int h  = (rb >> 11) & 15;          // (rb / L) % NH

    // slope = 2^(-0.5*(h+1))  (NH=16 is a power of two)
    const float slope = exp2f(-0.5f * (float)(h + 1));

    const int t  = threadIdx.x;              // 0..511
    const int j0 = t * 4;

    const long long base = (long long)rb * (long long)L;
    const float4* __restrict__ m4 = (const float4*)(mask + base);
    float4*       __restrict__ o4 = (float4*)(out + base);

    // Front-batched independent loads (rows are 512 float4 apart).
    float4 m[ROWS_PER_BLK];
    #pragma unroll
    for (int r = 0; r < ROWS_PER_BLK; r++)
        m[r] = m4[r * 512 + t];

    #pragma unroll
    for (int r = 0; r < ROWS_PER_BLK; r++) {
        const float fi = (float)(i0 + r);
        float4 o;
        o.x = m[r].x - slope * fabsf(fi - (float)(j0 + 0));
        o.y = m[r].y - slope * fabsf(fi - (float)(j0 + 1));
        o.z = m[r].z - slope * fabsf(fi - (float)(j0 + 2));
        o.w = m[r].w - slope * fabsf(fi - (float)(j0 + 3));
        __stcs(&o4[r * 512 + t], o);
    }
}

extern "C" void kernel_launch(void* const* d_in, const int* in_sizes, int n_in,
                              void* d_out, int out_size)
{
    const float* mask = (const float*)d_in[0];
    float* out = (float*)d_out;

    const int L = 2048;
    const long long total = (long long)in_sizes[0];        // B*NH*L*L
    const int rows = (int)(total / L);                     // 65536
    const int blocks = rows / ROWS_PER_BLK;                // 8192

    alibi_kernel<<<blocks, 512>>>(mask, out, L);
}

// round 16
// speedup vs baseline: 1.0135x; 1.0135x over previous
#include <cuda_runtime.h>
#include <cuda_bf16.h>

// out[b,h,i,j] = mask[b,h,i,j] - |slope(h) * (i - j)|
// B=2, NH=16, L=2048. HBM-bound: 512 MiB read + 512 MiB write.
//
// FINAL (= R3/R7, empirical best: 149.4-149.9us ncu, DRAM 85.7-86.0%,
// 155.9us harness). Full exploration matrix over 8 rounds:
//   - cache ops: ldcs+stcs BEST; default+stcs, ldcg+stcs, default+default worse
//   - occupancy: 39% (this config) beats 52/58/74% variants — DRAM queue
//     saturates at ~25 warps/SM; more residency only hurts locality
//   - persistence: grid-stride persistent blocks lose 6% (loop edges
//     serialize loads behind stores; fire-and-forget waves overlap them)
//   - MLP: 8 front-batched LDG.128/thread ~= 4 (slightly better), >8 no gain
// Conclusion: at the HBM mixed read+write turnaround ceiling (~6.8 TB/s).
//
//   - 8 contiguous rows per block (64KB contiguous footprint), 512 threads
//   - front-batched 8 independent LDG.128 per thread (MLP_p1=8)
//   - __ldcs / __stcs streaming hints (zero-reuse data, evict-first in L1+L2)
//   - non-persistent fire-and-forget blocks

#define ROWS_PER_BLK 8

__global__ __launch_bounds__(512) void alibi_kernel(
    const float* __restrict__ mask,
    float* __restrict__ out,
    int L)
{
    // Base row for this block; all 8 rows share (b,h) since L % 8 == 0.
    const int rb = blockIdx.x * ROWS_PER_BLK;
    const int i0 = rb & (2048 - 1);          // rb % L, L=2048
    const int h  = (rb >> 11) & 15;          // (rb / L) % NH

    // slope = 2^(-0.5*(h+1))  (NH=16 is a power of two)
    const float slope = exp2f(-0.5f * (float)(h + 1));

    const int t  = threadIdx.x;              // 0..511
    const int j0 = t * 4;

    const long long base = (long long)rb * (long long)L;
    const float4* __restrict__ m4 = (const float4*)(mask + base);
    float4*       __restrict__ o4 = (float4*)(out + base);

    // Front-batched independent streaming loads (rows are 512 float4 apart).
    float4 m[ROWS_PER_BLK];
    #pragma unroll
    for (int r = 0; r < ROWS_PER_BLK; r++)
        m[r] = __ldcs(&m4[r * 512 + t]);

    #pragma unroll
    for (int r = 0; r < ROWS_PER_BLK; r++) {
        const float fi = (float)(i0 + r);
        float4 o;
        o.x = m[r].x - slope * fabsf(fi - (float)(j0 + 0));
        o.y = m[r].y - slope * fabsf(fi - (float)(j0 + 1));
        o.z = m[r].z - slope * fabsf(fi - (float)(j0 + 2));
        o.w = m[r].w - slope * fabsf(fi - (float)(j0 + 3));
        __stcs(&o4[r * 512 + t], o);
    }
}

extern "C" void kernel_launch(void* const* d_in, const int* in_sizes, int n_in,
                              void* d_out, int out_size)
{
    const float* mask = (const float*)d_in[0];
    float* out = (float*)d_out;

    const int L = 2048;
    const long long total = (long long)in_sizes[0];        // B*NH*L*L
    const int rows = (int)(total / L);                     // 65536
    const int blocks = rows / ROWS_PER_BLK;                // 8192

    alibi_kernel<<<blocks, 512>>>(mask, out, L);
}